// round 7
// baseline (speedup 1.0000x reference)
#include <cuda_runtime.h>

#define ALPHA_F 0.1f

constexpr int Bb  = 32;
constexpr int Tt  = 2048;
constexpr int DIN = 128;
constexpr int Hh  = 512;
constexpr int CHUNK = 128;                 // timesteps per proj M-tile
constexpr int NCH  = Tt / CHUNK;           // 16 chunks per batch

// Scratch for x_proj_scaled = ALPHA * x @ I^T : [B*T, H] fp32 (128 MB)
__device__ float g_xproj[(size_t)Bb * Tt * Hh];
// Per (batch, chunk) completion counters (4 N-tiles each)
__device__ int g_cnt[Bb][NCH];

// ---------------- packed-f32x2 helpers ----------
#define PACK2(d, lo, hi)   asm("mov.b64 %0, {%1, %2};" : "=l"(d) : "f"(lo), "f"(hi))
#define UNPACK2(lo, hi, s) asm("mov.b64 {%0, %1}, %2;" : "=f"(lo), "=f"(hi) : "l"(s))
#define FMA2(d, a, b)      asm("fma.rn.f32x2 %0, %1, %2, %0;" : "+l"(d) : "l"(a), "l"(b))

__device__ __forceinline__ float tanh_fast(float x) {
    float y;
    asm("tanh.approx.f32 %0, %1;" : "=f"(y) : "f"(x));
    return y;
}

// atomic 64-bit shared store / volatile load (single-instruction => untorn)
__device__ __forceinline__ void sts64(unsigned addr, unsigned long long v) {
    asm volatile("st.shared.b64 [%0], %1;" :: "r"(addr), "l"(v) : "memory");
}
__device__ __forceinline__ unsigned long long lds64v(unsigned addr) {
    unsigned long long v;
    asm volatile("ld.volatile.shared.b64 %0, [%1];" : "=l"(v) : "r"(addr) : "memory");
    return v;
}

constexpr float FXSCALE = 8388608.0f;        // 2^23
constexpr float FXINV   = 1.0f / 8388608.0f;

constexpr int BM = 128, BN = 128, BK = 32;

__global__ void zero_cnt_kernel() {
    int i = threadIdx.x;
    if (i < Bb * NCH) ((int*)g_cnt)[i] = 0;
}

// consumer-side gate: wait until all 4 N-tiles of (b, chunk) are written
__device__ __forceinline__ void wait_chunk(int b, int c) {
    volatile int* p = &g_cnt[b][c];
    if (*p < 4) {
        while (*p < 4) __nanosleep(64);
    }
    __threadfence();   // acquire
}

// =====================================================================
// Fused kernel.
//  blocks [0,32):   scan, one batch each, 128 active threads
//  blocks [32,2080): proj tiles, ordered chunk-major then batch so early
//                    timesteps across all batches complete first.
// Scan cross-warp exchange: lock-free tagged STS.64 + volatile poll
// (parity double-buffered; skew bound <= 1 step proves no clobber).
// =====================================================================
__global__ __launch_bounds__(256, 2) void fused_kernel(const float* __restrict__ X,
                                                       const float* __restrict__ Iw,
                                                       const float* __restrict__ mw,
                                                       const float* __restrict__ nw,
                                                       float* __restrict__ out) {
    __shared__ float As[BK][BM + 4];
    __shared__ float Bs[BK][BN + 4];
    __shared__ unsigned long long wcom[2][4];  // [t&1][warp] -> (s1|tag, s0)

    const int bid = blockIdx.x;

    if (bid >= Bb) {
        // ================= PROJ TILE =================
        const int pbid = bid - Bb;           // 0..2047
        const int tc   = pbid >> 7;          // chunk 0..15
        const int rem  = pbid & 127;
        const int b    = rem >> 2;           // batch 0..31
        const int nc   = rem & 3;            // N tile 0..3
        const long long m0 = (long long)b * Tt + (long long)tc * CHUNK;
        const int       n0 = nc * BN;

        const int tid = threadIdx.x;
        const int tx  = tid & 15;
        const int ty  = tid >> 4;

        unsigned long long acc[8][4];
#pragma unroll
        for (int i = 0; i < 8; i++)
#pragma unroll
            for (int j = 0; j < 4; j++) acc[i][j] = 0ull;

        for (int kt = 0; kt < DIN; kt += BK) {
#pragma unroll
            for (int q = 0; q < 4; q++) {
                int p   = tid + q * 256;
                int row = p >> 3;
                int kq  = p & 7;
                float4 av = *(const float4*)(X + (m0 + row) * DIN + kt + kq * 4);
                As[kq * 4 + 0][row] = av.x; As[kq * 4 + 1][row] = av.y;
                As[kq * 4 + 2][row] = av.z; As[kq * 4 + 3][row] = av.w;
                float4 bv = *(const float4*)(Iw + (long long)(n0 + row) * DIN + kt + kq * 4);
                // fold ALPHA into the I operand
                Bs[kq * 4 + 0][row] = ALPHA_F * bv.x; Bs[kq * 4 + 1][row] = ALPHA_F * bv.y;
                Bs[kq * 4 + 2][row] = ALPHA_F * bv.z; Bs[kq * 4 + 3][row] = ALPHA_F * bv.w;
            }
            __syncthreads();

#pragma unroll
            for (int k = 0; k < BK; k++) {
                float4 a0 = *(const float4*)&As[k][ty * 8];
                float4 a1 = *(const float4*)&As[k][ty * 8 + 4];
                const unsigned long long* bp =
                    (const unsigned long long*)&Bs[k][tx * 8];
                unsigned long long pb0 = bp[0], pb1 = bp[1], pb2 = bp[2], pb3 = bp[3];
                float av[8] = {a0.x, a0.y, a0.z, a0.w, a1.x, a1.y, a1.z, a1.w};
#pragma unroll
                for (int i = 0; i < 8; i++) {
                    unsigned long long pa;
                    PACK2(pa, av[i], av[i]);
                    FMA2(acc[i][0], pa, pb0);
                    FMA2(acc[i][1], pa, pb1);
                    FMA2(acc[i][2], pa, pb2);
                    FMA2(acc[i][3], pa, pb3);
                }
            }
            __syncthreads();
        }

#pragma unroll
        for (int i = 0; i < 8; i++) {
            float4 o0, o1;
            UNPACK2(o0.x, o0.y, acc[i][0]);
            UNPACK2(o0.z, o0.w, acc[i][1]);
            UNPACK2(o1.x, o1.y, acc[i][2]);
            UNPACK2(o1.z, o1.w, acc[i][3]);
            long long row = m0 + ty * 8 + i;
            float* op = g_xproj + row * Hh + n0 + tx * 8;
            *(float4*)op       = o0;
            *(float4*)(op + 4) = o1;
        }

        // publish: all writes visible, then bump (b, tc) counter
        __threadfence();
        __syncthreads();
        if (tid == 0) atomicAdd(&g_cnt[b][tc], 1);
        return;
    }

    // ================= SCAN =================
    if (threadIdx.x >= 128) return;   // 128 active threads

    const int b    = bid;
    const int tid  = threadIdx.x;
    const int wid  = tid >> 5;
    const int lane = tid & 31;

    // init exchange slots to a non-matching tag (3 != 0, 3 != 1)
    if (tid < 8) ((unsigned long long*)wcom)[tid] = 0x0000000300000000ull;
    unsigned wcom_base = (unsigned)__cvta_generic_to_shared(&wcom[0][0]);
    __syncthreads();

    float h0v = 0.f, h1v = 0.f, h2v = 0.f, h3v = 0.f;
    const int i0 = tid * 4;
    float am0[4], am1[4], n0[4], n1[4];
#pragma unroll
    for (int j = 0; j < 4; j++) {
        am0[j] = (ALPHA_F * FXINV) * mw[(i0 + j) * 2 + 0];
        am1[j] = (ALPHA_F * FXINV) * mw[(i0 + j) * 2 + 1];
        n0[j]  = FXSCALE * nw[(i0 + j) * 2 + 0];
        n1[j]  = FXSCALE * nw[(i0 + j) * 2 + 1];
    }
    const float4* xp4  = (const float4*)(g_xproj + (size_t)b * Tt * Hh);
    float*        outb = out + (size_t)b * Tt * Hh;

    // other-warp slot offsets (within a parity bank of 4 slots)
    const int w1 = (wid + 1) & 3, w2 = (wid + 2) & 3, w3 = (wid + 3) & 3;

    // first chunk must be ready before the initial ring fill
    wait_chunk(b, 0);

    // 4-deep prefetch ring
    float4 ring[4];
#pragma unroll
    for (int j = 0; j < 4; j++) ring[j] = xp4[(size_t)j * (Hh / 4) + tid];

#pragma unroll 4
    for (int t = 0; t < Tt; t++) {
        const int slot = t & 3;
        float4 xp = ring[slot];

        // -- critical path: tanh -> local dot (pre-scaled) -> f2i -> REDUX --
        float th0 = tanh_fast(h0v), th1 = tanh_fast(h1v);
        float th2 = tanh_fast(h2v), th3 = tanh_fast(h3v);
        float s0f = fmaf(th0, n0[0], th1 * n0[1]) + fmaf(th2, n0[2], th3 * n0[3]);
        float s1f = fmaf(th0, n1[0], th1 * n1[1]) + fmaf(th2, n1[2], th3 * n1[3]);
        int s0 = __reduce_add_sync(0xffffffffu, __float2int_rn(s0f));
        int s1 = __reduce_add_sync(0xffffffffu, __float2int_rn(s1f));

        // publish (s0, s1 with 2-bit step tag) as one atomic STS.64
        const unsigned tag  = (unsigned)(t & 3);
        const unsigned bank = wcom_base + (unsigned)((t & 1) * 32);
        if (lane == 0) {
            unsigned hi = ((unsigned)s1 & ~3u) | tag;
            sts64(bank + wid * 8, ((unsigned long long)hi << 32) | (unsigned)s0);
        }

        // ---- poll shadow: prefetch ring refill ----
        {
            int tp = t + 4;
            if (tp < Tt) {
                if ((tp & (CHUNK - 1)) == 0) wait_chunk(b, tp >> 7);
            } else {
                tp = Tt - 1;
            }
            ring[slot] = xp4[(size_t)tp * (Hh / 4) + tid];
        }

        // ---- poll the other 3 warps' slots ----
        unsigned long long v1, v2, v3;
        do { v1 = lds64v(bank + w1 * 8); } while (((unsigned)(v1 >> 32) & 3u) != tag);
        do { v2 = lds64v(bank + w2 * 8); } while (((unsigned)(v2 >> 32) & 3u) != tag);
        do { v3 = lds64v(bank + w3 * 8); } while (((unsigned)(v3 >> 32) & 3u) != tag);

        int S0i = s0 + (int)(unsigned)v1 + (int)(unsigned)v2 + (int)(unsigned)v3;
        int S1i = s1 + ((int)(v1 >> 32) & ~3) + ((int)(v2 >> 32) & ~3)
                     + ((int)(v3 >> 32) & ~3);
        float S0 = (float)S0i;
        float S1 = (float)S1i;

        // h = 0.9*h + (a*m0/2^23)S0 + (a*m1/2^23)S1 + xp   (xp pre-scaled by a)
        h0v = fmaf(h0v, 1.0f - ALPHA_F, fmaf(am0[0], S0, fmaf(am1[0], S1, xp.x)));
        h1v = fmaf(h1v, 1.0f - ALPHA_F, fmaf(am0[1], S0, fmaf(am1[1], S1, xp.y)));
        h2v = fmaf(h2v, 1.0f - ALPHA_F, fmaf(am0[2], S0, fmaf(am1[2], S1, xp.z)));
        h3v = fmaf(h3v, 1.0f - ALPHA_F, fmaf(am0[3], S0, fmaf(am1[3], S1, xp.w)));

        *(float4*)&outb[(size_t)t * Hh + i0] = make_float4(h0v, h1v, h2v, h3v);
    }
}

// =====================================================================
extern "C" void kernel_launch(void* const* d_in, const int* in_sizes, int n_in,
                              void* d_out, int out_size) {
    const float* x  = (const float*)d_in[0];  // [32, 2048, 128]
    const float* m  = (const float*)d_in[1];  // [512, 2]
    const float* n  = (const float*)d_in[2];  // [512, 2]
    const float* Iw = (const float*)d_in[3];  // [512, 128]
    float* out = (float*)d_out;               // [32, 2048, 512]

    zero_cnt_kernel<<<1, 512>>>();
    fused_kernel<<<Bb + (Bb * NCH * 4), 256>>>(x, Iw, m, n, out);
}

// round 8
// speedup vs baseline: 1.6852x; 1.6852x over previous
#include <cuda_runtime.h>

#define ALPHA_F 0.1f

constexpr int Bb  = 32;
constexpr int Tt  = 2048;
constexpr int DIN = 128;
constexpr int Hh  = 512;
constexpr int CHUNK = 128;                 // timesteps per proj M-tile
constexpr int NCH  = Tt / CHUNK;           // 16 chunks per batch

// Scratch for x_proj_scaled = ALPHA * x @ I^T : [B*T, H] fp32 (128 MB)
__device__ float g_xproj[(size_t)Bb * Tt * Hh];
// Per (batch, chunk) completion counters (4 N-tiles each)
__device__ int g_cnt[Bb][NCH];

// ---------------- packed-f32x2 helpers ----------
#define PACK2(d, lo, hi)   asm("mov.b64 %0, {%1, %2};" : "=l"(d) : "f"(lo), "f"(hi))
#define UNPACK2(lo, hi, s) asm("mov.b64 {%0, %1}, %2;" : "=f"(lo), "=f"(hi) : "l"(s))
#define FMA2(d, a, b)      asm("fma.rn.f32x2 %0, %1, %2, %0;" : "+l"(d) : "l"(a), "l"(b))

__device__ __forceinline__ float tanh_fast(float x) {
    float y;
    asm("tanh.approx.f32 %0, %1;" : "=f"(y) : "f"(x));
    return y;
}

constexpr float FXSCALE = 8388608.0f;        // 2^23
constexpr float FXINV   = 1.0f / 8388608.0f;

constexpr int BM = 128, BN = 128, BK = 32;

__global__ void zero_cnt_kernel() {
    int i = threadIdx.x;
    if (i < Bb * NCH) ((int*)g_cnt)[i] = 0;
}

// consumer-side gate: wait until all 4 N-tiles of (b, chunk) are written
__device__ __forceinline__ void wait_chunk(int b, int c) {
    volatile int* p = &g_cnt[b][c];
    if (*p < 4) {
        while (*p < 4) __nanosleep(64);
    }
    __threadfence();   // acquire
}

// =====================================================================
// Fused kernel, ONE block per SM (launch_bounds occ=1):
//  blocks [0,32):   scan, one batch each, 128 active threads — each on a
//                   PRIVATE SM (wave-1 placement), zero proj contention.
//  blocks [32,2080): proj tiles on the remaining ~116 SMs, ordered
//                   chunk-major then batch so early timesteps land first.
// =====================================================================
__global__ __launch_bounds__(256, 1) void fused_kernel(const float* __restrict__ X,
                                                       const float* __restrict__ Iw,
                                                       const float* __restrict__ mw,
                                                       const float* __restrict__ nw,
                                                       float* __restrict__ out) {
    __shared__ float As[BK][BM + 4];
    __shared__ float Bs[BK][BN + 4];
    __shared__ int4  wsum[2][2];

    const int bid = blockIdx.x;

    if (bid >= Bb) {
        // ================= PROJ TILE =================
        const int pbid = bid - Bb;           // 0..2047
        const int tc   = pbid >> 7;          // chunk 0..15
        const int rem  = pbid & 127;
        const int b    = rem >> 2;           // batch 0..31
        const int nc   = rem & 3;            // N tile 0..3
        const long long m0 = (long long)b * Tt + (long long)tc * CHUNK;
        const int       n0 = nc * BN;

        const int tid = threadIdx.x;
        const int tx  = tid & 15;
        const int ty  = tid >> 4;

        unsigned long long acc[8][4];
#pragma unroll
        for (int i = 0; i < 8; i++)
#pragma unroll
            for (int j = 0; j < 4; j++) acc[i][j] = 0ull;

        for (int kt = 0; kt < DIN; kt += BK) {
#pragma unroll
            for (int q = 0; q < 4; q++) {
                int p   = tid + q * 256;
                int row = p >> 3;
                int kq  = p & 7;
                float4 av = *(const float4*)(X + (m0 + row) * DIN + kt + kq * 4);
                As[kq * 4 + 0][row] = av.x; As[kq * 4 + 1][row] = av.y;
                As[kq * 4 + 2][row] = av.z; As[kq * 4 + 3][row] = av.w;
                float4 bv = *(const float4*)(Iw + (long long)(n0 + row) * DIN + kt + kq * 4);
                // fold ALPHA into the I operand
                Bs[kq * 4 + 0][row] = ALPHA_F * bv.x; Bs[kq * 4 + 1][row] = ALPHA_F * bv.y;
                Bs[kq * 4 + 2][row] = ALPHA_F * bv.z; Bs[kq * 4 + 3][row] = ALPHA_F * bv.w;
            }
            __syncthreads();

#pragma unroll
            for (int k = 0; k < BK; k++) {
                float4 a0 = *(const float4*)&As[k][ty * 8];
                float4 a1 = *(const float4*)&As[k][ty * 8 + 4];
                const unsigned long long* bp =
                    (const unsigned long long*)&Bs[k][tx * 8];
                unsigned long long pb0 = bp[0], pb1 = bp[1], pb2 = bp[2], pb3 = bp[3];
                float av[8] = {a0.x, a0.y, a0.z, a0.w, a1.x, a1.y, a1.z, a1.w};
#pragma unroll
                for (int i = 0; i < 8; i++) {
                    unsigned long long pa;
                    PACK2(pa, av[i], av[i]);
                    FMA2(acc[i][0], pa, pb0);
                    FMA2(acc[i][1], pa, pb1);
                    FMA2(acc[i][2], pa, pb2);
                    FMA2(acc[i][3], pa, pb3);
                }
            }
            __syncthreads();
        }

#pragma unroll
        for (int i = 0; i < 8; i++) {
            float4 o0, o1;
            UNPACK2(o0.x, o0.y, acc[i][0]);
            UNPACK2(o0.z, o0.w, acc[i][1]);
            UNPACK2(o1.x, o1.y, acc[i][2]);
            UNPACK2(o1.z, o1.w, acc[i][3]);
            long long row = m0 + ty * 8 + i;
            float* op = g_xproj + row * Hh + n0 + tx * 8;
            *(float4*)op       = o0;
            *(float4*)(op + 4) = o1;
        }

        // publish: all writes visible, then bump (b, tc) counter
        __threadfence();
        __syncthreads();
        if (tid == 0) atomicAdd(&g_cnt[b][tc], 1);
        return;
    }

    // ================= SCAN =================
    if (threadIdx.x >= 128) return;   // 128 active threads

    const int b    = bid;
    const int tid  = threadIdx.x;
    const int wid  = tid >> 5;
    const int lane = tid & 31;

    float h0v = 0.f, h1v = 0.f, h2v = 0.f, h3v = 0.f;
    const int i0 = tid * 4;
    float am0[4], am1[4], n0[4], n1[4];
#pragma unroll
    for (int j = 0; j < 4; j++) {
        am0[j] = (ALPHA_F * FXINV) * mw[(i0 + j) * 2 + 0];
        am1[j] = (ALPHA_F * FXINV) * mw[(i0 + j) * 2 + 1];
        n0[j]  = FXSCALE * nw[(i0 + j) * 2 + 0];
        n1[j]  = FXSCALE * nw[(i0 + j) * 2 + 1];
    }
    const float4* xp4  = (const float4*)(g_xproj + (size_t)b * Tt * Hh);
    float*        outb = out + (size_t)b * Tt * Hh;

    // first chunk must be ready before the initial ring fill
    wait_chunk(b, 0);

    // 4-deep prefetch ring
    float4 ring[4];
#pragma unroll
    for (int j = 0; j < 4; j++) ring[j] = xp4[(size_t)j * (Hh / 4) + tid];

#pragma unroll 4
    for (int t = 0; t < Tt; t++) {
        const int slot = t & 3;
        float4 xp = ring[slot];
        {
            int tp = t + 4;
            if (tp < Tt) {
                if ((tp & (CHUNK - 1)) == 0) wait_chunk(b, tp >> 7);
            } else {
                tp = Tt - 1;
            }
            ring[slot] = xp4[(size_t)tp * (Hh / 4) + tid];
        }

        // -- critical path: tanh -> local dot (pre-scaled) -> f2i -> REDUX --
        float th0 = tanh_fast(h0v), th1 = tanh_fast(h1v);
        float th2 = tanh_fast(h2v), th3 = tanh_fast(h3v);
        float s0f = fmaf(th0, n0[0], th1 * n0[1]) + fmaf(th2, n0[2], th3 * n0[3]);
        float s1f = fmaf(th0, n1[0], th1 * n1[1]) + fmaf(th2, n1[2], th3 * n1[3]);
        int s0 = __reduce_add_sync(0xffffffffu, __float2int_rn(s0f));
        int s1 = __reduce_add_sync(0xffffffffu, __float2int_rn(s1f));

        const int buf = t & 1;
        if (lane == 0) {
            int* w = (int*)&wsum[buf][0];
            w[wid * 2 + 0] = s0;
            w[wid * 2 + 1] = s1;
        }
        __syncthreads();
        int4 p0 = wsum[buf][0];
        int4 p1 = wsum[buf][1];
        float S0 = (float)((p0.x + p0.z) + (p1.x + p1.z));  // still x2^23
        float S1 = (float)((p0.y + p0.w) + (p1.y + p1.w));

        // h = 0.9*h + (a*m0/2^23)S0 + (a*m1/2^23)S1 + xp   (xp pre-scaled by a)
        h0v = fmaf(h0v, 1.0f - ALPHA_F, fmaf(am0[0], S0, fmaf(am1[0], S1, xp.x)));
        h1v = fmaf(h1v, 1.0f - ALPHA_F, fmaf(am0[1], S0, fmaf(am1[1], S1, xp.y)));
        h2v = fmaf(h2v, 1.0f - ALPHA_F, fmaf(am0[2], S0, fmaf(am1[2], S1, xp.z)));
        h3v = fmaf(h3v, 1.0f - ALPHA_F, fmaf(am0[3], S0, fmaf(am1[3], S1, xp.w)));

        *(float4*)&outb[(size_t)t * Hh + i0] = make_float4(h0v, h1v, h2v, h3v);
    }
}

// =====================================================================
extern "C" void kernel_launch(void* const* d_in, const int* in_sizes, int n_in,
                              void* d_out, int out_size) {
    const float* x  = (const float*)d_in[0];  // [32, 2048, 128]
    const float* m  = (const float*)d_in[1];  // [512, 2]
    const float* n  = (const float*)d_in[2];  // [512, 2]
    const float* Iw = (const float*)d_in[3];  // [512, 128]
    float* out = (float*)d_out;               // [32, 2048, 512]

    zero_cnt_kernel<<<1, 512>>>();
    fused_kernel<<<Bb + (Bb * NCH * 4), 256>>>(x, Iw, m, n, out);
}